// round 15
// baseline (speedup 1.0000x reference)
#include <cuda_runtime.h>
#include <cstdint>

#define LUT_MAX 512   // actual LUT is 302 entries
#define BLOCK   512   // flat optimum; 256/512/1024 all within the noise band

// FINAL — converged. Identical source: 44.96/45.15/45.66/45.92/46.14 us over
// five runs (NAT-clock DVFS noise; mean 45.6, range 1.2). DRAM-bound at
// 6.2-6.35 TB/s = 78-80% of HBM3e spec — the turnaround-limited ceiling for
// this 3-read/2-write once-touched stream. Controlled experiments rejected:
// grid-stride, 2xfloat4 (interleaved + contiguous), .cs hints (reads/writes/
// both), asm-pinned loads, BLOCK=256/1024. TMA staging ruled out by measured
// LTS path-independence. Byte traffic provably minimal (labels shared across
// both outputs; kernel split would re-read labels).
template <bool MASK_AS_FLOAT, bool EXACT>
__global__ __launch_bounds__(BLOCK)
void octvol_kernel(const int4* __restrict__ labels4,
                   const float4* __restrict__ par4,
                   const float4* __restrict__ tex4,
                   const float* __restrict__ lut,
                   int lut_n,
                   float4* __restrict__ out_vol4,
                   void* __restrict__ out_mask,
                   int n4)
{
    __shared__ float s_lut[LUT_MAX];
    for (int i = threadIdx.x; i < lut_n; i += blockDim.x)
        s_lut[i] = lut[i];
    __syncthreads();

    int idx = blockIdx.x * blockDim.x + threadIdx.x;
    if (!EXACT && idx >= n4) return;

    int4   lb = labels4[idx];
    float4 pa = par4[idx];
    float4 tx = tex4[idx];

    float s0 = s_lut[lb.x];
    float s1 = s_lut[lb.y];
    float s2 = s_lut[lb.z];
    float s3 = s_lut[lb.w];

    float v0 = s0 * tx.x; if (v0 == 0.0f) v0 = 1.0f;
    float v1 = s1 * tx.y; if (v1 == 0.0f) v1 = 1.0f;
    float v2 = s2 * tx.z; if (v2 == 0.0f) v2 = 1.0f;
    float v3 = s3 * tx.w; if (v3 == 0.0f) v3 = 1.0f;

    float4 o;
    o.x = pa.x * v0;
    o.y = pa.y * v1;
    o.z = pa.z * v2;
    o.w = pa.w * v3;
    out_vol4[idx] = o;

    if (MASK_AS_FLOAT) {
        float4 m;
        m.x = lb.x ? 1.0f : 0.0f;
        m.y = lb.y ? 1.0f : 0.0f;
        m.z = lb.z ? 1.0f : 0.0f;
        m.w = lb.w ? 1.0f : 0.0f;
        reinterpret_cast<float4*>(out_mask)[idx] = m;
    } else {
        uchar4 m;
        m.x = lb.x ? 1 : 0;
        m.y = lb.y ? 1 : 0;
        m.z = lb.z ? 1 : 0;
        m.w = lb.w ? 1 : 0;
        reinterpret_cast<uchar4*>(out_mask)[idx] = m;
    }
}

extern "C" void kernel_launch(void* const* d_in, const int* in_sizes, int n_in,
                              void* d_out, int out_size)
{
    // metadata order:
    //   0: vessel_labels  int32  [N]
    //   1: parenchyma     f32    [N]
    //   2: vessel_texture f32    [N]
    //   3: intensity_lut  f32    [302]
    const int*   labels = (const int*)  d_in[0];
    const float* par    = (const float*)d_in[1];
    const float* tex    = (const float*)d_in[2];
    const float* lut    = (const float*)d_in[3];

    int n     = in_sizes[0];
    int lut_n = in_sizes[3];
    int n4    = n / 4;

    float* out_vol = (float*)d_out;

    dim3 block(BLOCK);
    dim3 grid((n4 + BLOCK - 1) / BLOCK);
    bool exact = (n4 % BLOCK) == 0;

    if (out_size >= 2 * n) {
        void* out_mask = (void*)(out_vol + n);
        if (exact)
            octvol_kernel<true, true><<<grid, block>>>(
                (const int4*)labels, (const float4*)par, (const float4*)tex,
                lut, lut_n, (float4*)out_vol, out_mask, n4);
        else
            octvol_kernel<true, false><<<grid, block>>>(
                (const int4*)labels, (const float4*)par, (const float4*)tex,
                lut, lut_n, (float4*)out_vol, out_mask, n4);
    } else {
        void* out_mask = (void*)((char*)d_out + (size_t)n * sizeof(float));
        if (exact)
            octvol_kernel<false, true><<<grid, block>>>(
                (const int4*)labels, (const float4*)par, (const float4*)tex,
                lut, lut_n, (float4*)out_vol, out_mask, n4);
        else
            octvol_kernel<false, false><<<grid, block>>>(
                (const int4*)labels, (const float4*)par, (const float4*)tex,
                lut, lut_n, (float4*)out_vol, out_mask, n4);
    }
}

// round 16
// speedup vs baseline: 1.0126x; 1.0126x over previous
#include <cuda_runtime.h>
#include <cstdint>

#define LUT_MAX 512   // actual LUT is 302 entries
#define BLOCK   512   // flat optimum; 256/512/1024 all within the noise band

// FINAL — converged at the HBM roofline. Identical source measured
// 44.86/44.96/45.15/45.66/45.92/46.14 us over six runs (NAT-clock DVFS noise;
// mean 45.45, range 1.28 — both extremes from byte-identical binaries).
// DRAM-bound at 6.2-6.35 TB/s = 78-80% of HBM3e spec, the turnaround-limited
// ceiling for this 3-read/2-write once-touched 320MB stream. Controlled
// experiments rejected: grid-stride, 2xfloat4 (interleaved + contiguous),
// .cs hints (reads/writes/both), asm-pinned loads, BLOCK=256/1024. TMA
// staging ruled out by measured LTS path-independence (LDG/STG == TMA).
// Byte traffic provably minimal (labels shared across both outputs).
template <bool MASK_AS_FLOAT, bool EXACT>
__global__ __launch_bounds__(BLOCK)
void octvol_kernel(const int4* __restrict__ labels4,
                   const float4* __restrict__ par4,
                   const float4* __restrict__ tex4,
                   const float* __restrict__ lut,
                   int lut_n,
                   float4* __restrict__ out_vol4,
                   void* __restrict__ out_mask,
                   int n4)
{
    __shared__ float s_lut[LUT_MAX];
    for (int i = threadIdx.x; i < lut_n; i += blockDim.x)
        s_lut[i] = lut[i];
    __syncthreads();

    int idx = blockIdx.x * blockDim.x + threadIdx.x;
    if (!EXACT && idx >= n4) return;

    int4   lb = labels4[idx];
    float4 pa = par4[idx];
    float4 tx = tex4[idx];

    float s0 = s_lut[lb.x];
    float s1 = s_lut[lb.y];
    float s2 = s_lut[lb.z];
    float s3 = s_lut[lb.w];

    float v0 = s0 * tx.x; if (v0 == 0.0f) v0 = 1.0f;
    float v1 = s1 * tx.y; if (v1 == 0.0f) v1 = 1.0f;
    float v2 = s2 * tx.z; if (v2 == 0.0f) v2 = 1.0f;
    float v3 = s3 * tx.w; if (v3 == 0.0f) v3 = 1.0f;

    float4 o;
    o.x = pa.x * v0;
    o.y = pa.y * v1;
    o.z = pa.z * v2;
    o.w = pa.w * v3;
    out_vol4[idx] = o;

    if (MASK_AS_FLOAT) {
        float4 m;
        m.x = lb.x ? 1.0f : 0.0f;
        m.y = lb.y ? 1.0f : 0.0f;
        m.z = lb.z ? 1.0f : 0.0f;
        m.w = lb.w ? 1.0f : 0.0f;
        reinterpret_cast<float4*>(out_mask)[idx] = m;
    } else {
        uchar4 m;
        m.x = lb.x ? 1 : 0;
        m.y = lb.y ? 1 : 0;
        m.z = lb.z ? 1 : 0;
        m.w = lb.w ? 1 : 0;
        reinterpret_cast<uchar4*>(out_mask)[idx] = m;
    }
}

extern "C" void kernel_launch(void* const* d_in, const int* in_sizes, int n_in,
                              void* d_out, int out_size)
{
    // metadata order:
    //   0: vessel_labels  int32  [N]
    //   1: parenchyma     f32    [N]
    //   2: vessel_texture f32    [N]
    //   3: intensity_lut  f32    [302]
    const int*   labels = (const int*)  d_in[0];
    const float* par    = (const float*)d_in[1];
    const float* tex    = (const float*)d_in[2];
    const float* lut    = (const float*)d_in[3];

    int n     = in_sizes[0];
    int lut_n = in_sizes[3];
    int n4    = n / 4;

    float* out_vol = (float*)d_out;

    dim3 block(BLOCK);
    dim3 grid((n4 + BLOCK - 1) / BLOCK);
    bool exact = (n4 % BLOCK) == 0;

    if (out_size >= 2 * n) {
        void* out_mask = (void*)(out_vol + n);
        if (exact)
            octvol_kernel<true, true><<<grid, block>>>(
                (const int4*)labels, (const float4*)par, (const float4*)tex,
                lut, lut_n, (float4*)out_vol, out_mask, n4);
        else
            octvol_kernel<true, false><<<grid, block>>>(
                (const int4*)labels, (const float4*)par, (const float4*)tex,
                lut, lut_n, (float4*)out_vol, out_mask, n4);
    } else {
        void* out_mask = (void*)((char*)d_out + (size_t)n * sizeof(float));
        if (exact)
            octvol_kernel<false, true><<<grid, block>>>(
                (const int4*)labels, (const float4*)par, (const float4*)tex,
                lut, lut_n, (float4*)out_vol, out_mask, n4);
        else
            octvol_kernel<false, false><<<grid, block>>>(
                (const int4*)labels, (const float4*)par, (const float4*)tex,
                lut, lut_n, (float4*)out_vol, out_mask, n4);
    }
}